// round 3
// baseline (speedup 1.0000x reference)
#include <cuda_runtime.h>

#define MAXN 131072
#define HID 128

// Per-node packed state: .x = dinv, .y = dx (=dinv*x), .z = ssum, .w = gsum
__device__ float4 g_node[MAXN];
__device__ int    g_deg[MAXN];
__device__ float  g_v[HID];

__global__ void k_zero(int n) {
    int i = blockIdx.x * blockDim.x + threadIdx.x;
    if (i < n) {
        g_deg[i]  = 0;
        g_node[i] = make_float4(0.f, 0.f, 0.f, 0.f);
    }
    if (i < HID) g_v[i] = 0.0f;
}

// Pass 1: in-degree histogram over destinations, int4-vectorized (4 edges/thread)
__global__ void k_deg(const int4* __restrict__ col4, int E4, int E) {
    int i = blockIdx.x * blockDim.x + threadIdx.x;
    if (i < E4) {
        int4 c = col4[i];
        atomicAdd(&g_deg[c.x], 1);
        atomicAdd(&g_deg[c.y], 1);
        atomicAdd(&g_deg[c.z], 1);
        atomicAdd(&g_deg[c.w], 1);
    }
    // remainder (E not divisible by 4)
    int r = E4 * 4 + i;
    if (i < (E & 3) && r < E) {
        atomicAdd(&g_deg[((const int*)col4)[r]], 1);
    }
}

// Pass 2: dinv = rsqrt(deg+1), dx = dinv * x  (writes .x,.y of node struct)
__global__ void k_dinv(const float* __restrict__ x, int n) {
    int i = blockIdx.x * blockDim.x + threadIdx.x;
    if (i < n) {
        float di = rsqrtf((float)(g_deg[i] + 1));
        *reinterpret_cast<float2*>(&g_node[i]) = make_float2(di, di * x[i]);
    }
}

// Pass 3: edge scatter, 4 edges/thread.
//   node[c].ssum += node[r].dx ;  node[r].gsum += node[c].dinv
// Gather at c (.x) and atomic at c (.z) share a 32B sector; same for r.
__global__ void k_scatter(const int4* __restrict__ row4,
                          const int4* __restrict__ col4, int E4, int E) {
    int i = blockIdx.x * blockDim.x + threadIdx.x;
    if (i < E4) {
        int4 r = row4[i];
        int4 c = col4[i];
        // batch gathers first for MLP
        float dx0 = g_node[r.x].y, dx1 = g_node[r.y].y,
              dx2 = g_node[r.z].y, dx3 = g_node[r.w].y;
        float di0 = g_node[c.x].x, di1 = g_node[c.y].x,
              di2 = g_node[c.z].x, di3 = g_node[c.w].x;
        atomicAdd(&g_node[c.x].z, dx0);
        atomicAdd(&g_node[c.y].z, dx1);
        atomicAdd(&g_node[c.z].z, dx2);
        atomicAdd(&g_node[c.w].z, dx3);
        atomicAdd(&g_node[r.x].w, di0);
        atomicAdd(&g_node[r.y].w, di1);
        atomicAdd(&g_node[r.z].w, di2);
        atomicAdd(&g_node[r.w].w, di3);
    }
    int t = E4 * 4 + i;
    if (i < (E & 3) && t < E) {
        int rr = ((const int*)row4)[t];
        int cc = ((const int*)col4)[t];
        atomicAdd(&g_node[cc].z, g_node[rr].y);
        atomicAdd(&g_node[rr].w, g_node[cc].x);
    }
}

// Pass 4: v[f] = sum_r g[r] * relu(W1[f]*s[r] + b1[f])
//   s[r] = di*(ssum + di*x) = di*(ssum + dx)   -> n.x*(n.z + n.y)
//   g[r] = di*(gsum + di)                       -> n.x*(n.w + n.x)
__global__ void __launch_bounds__(HID) k_vred(const float* __restrict__ W1,
                                              const float* __restrict__ b1,
                                              int n) {
    __shared__ float sh_s[HID];
    __shared__ float sh_g[HID];
    int f = threadIdx.x;
    float w  = W1[f];
    float bb = b1[f];
    float acc = 0.0f;

    for (int base = blockIdx.x * HID; base < n; base += gridDim.x * HID) {
        int r = base + f;
        float sv = 0.0f, gv = 0.0f;
        if (r < n) {
            float4 nd = g_node[r];
            sv = nd.x * (nd.z + nd.y);
            gv = nd.x * (nd.w + nd.x);
        }
        __syncthreads();
        sh_s[f] = sv;
        sh_g[f] = gv;
        __syncthreads();
        int m = n - base; if (m > HID) m = HID;
        #pragma unroll 8
        for (int j = 0; j < m; j++) {
            acc += sh_g[j] * fmaxf(fmaf(w, sh_s[j], bb), 0.0f);
        }
    }
    atomicAdd(&g_v[f], acc);
}

// Pass 5: out[o] = b2[o] + (1/N) * sum_f v[f] * W2[f, o]
__global__ void k_out(const float* __restrict__ W2,
                      const float* __restrict__ b2,
                      float* __restrict__ out,
                      int out_dim, float inv_n) {
    int o = blockIdx.x * blockDim.x + threadIdx.x;
    if (o >= out_dim) return;
    float acc = 0.0f;
    #pragma unroll 8
    for (int f = 0; f < HID; f++) {
        acc += g_v[f] * W2[f * out_dim + o];
    }
    out[o] = b2[o] + acc * inv_n;
}

extern "C" void kernel_launch(void* const* d_in, const int* in_sizes, int n_in,
                              void* d_out, int out_size) {
    const float* x    = (const float*)d_in[0];        // [N,1]
    const int*   ei   = (const int*)  d_in[1];        // [2,E]
    const float* W1   = (const float*)d_in[2];        // [1,128]
    const float* b1   = (const float*)d_in[3];        // [128]
    const float* W2   = (const float*)d_in[4];        // [128,400]
    const float* b2   = (const float*)d_in[5];        // [400]
    float*       out  = (float*)d_out;                // [400]

    int N = in_sizes[0];
    int E = in_sizes[1] / 2;
    const int* row = ei;
    const int* col = ei + E;
    int E4 = E / 4;

    int tb = 256;
    k_zero<<<(N + tb - 1) / tb, tb>>>(N);
    k_deg<<<(E4 + tb - 1) / tb, tb>>>((const int4*)col, E4, E);
    k_dinv<<<(N + tb - 1) / tb, tb>>>(x, N);
    k_scatter<<<(E4 + tb - 1) / tb, tb>>>((const int4*)row, (const int4*)col, E4, E);
    k_vred<<<296, HID>>>(W1, b1, N);
    k_out<<<(out_size + 127) / 128, 128>>>(W2, b2, out, out_size, 1.0f / (float)N);
}